// round 16
// baseline (speedup 1.0000x reference)
#include <cuda_runtime.h>
#include <math.h>

#define NMAX  8192
#define NBKT  1024
#define TPB   896     // 28 warps; 1 warp = 1 adjacent-rank row pair (2q, 2q+1)
#define SLOTS 28
#define GMAX  512
#define SMEM_BYTES (NMAX * 2 * sizeof(float))   // 64 KB: su (32K) + sz (32K)

__device__ float st_u [NMAX];         // sorted-by-yt: u = yp*20*log2e
__device__ float st_z [NMAX];         // z = -u*yt
__device__ float st_yt[NMAX];         // sorted yt
__device__ int   g_boff[NBKT + 1];    // bucket rank offsets
__device__ float g_ymin;
__device__ float2 g_part[GMAX];
__device__ int   g_done;              // zero-init; reset by last block each run

__device__ __forceinline__ float ex2a(float x) {
    float r; asm("ex2.approx.f32 %0, %1;" : "=f"(r) : "f"(x)); return r;
}

// ------------- Prep: counting sort staged through smem ----------------------
__global__ void __launch_bounds__(1024) pro_prep(const float* __restrict__ pred,
                                                 const float* __restrict__ ytg,
                                                 int n, int padn)
{
    __shared__ int   HA[NBKT], HB[NBKT];   // 8 KB
    __shared__ float SG[NMAX];             // 32 KB stage
    __shared__ float smn[32];
    const float K1 = 28.853900817779268f;  // 20 * log2(e)
    int t = threadIdx.x;

    HA[t] = 0;
    __syncthreads();

    float ry[8], rp[8];
    int   rb[8], rpos[8];
    float mn = 1e30f;

    #pragma unroll
    for (int e = 0; e < 8; e++) {
        int i = t + e * 1024;
        if (i < n) {
            float y = ytg[i], p = pred[i];
            ry[e] = y; rp[e] = p;
            int b = min(NBKT - 1, max(0, (int)floorf(y * (float)NBKT)));
            rb[e] = b;
            atomicAdd(&HA[b], 1);
            mn = fminf(mn, y);
        } else { ry[e] = 0.f; rp[e] = 0.f; rb[e] = -1; }
    }
    __syncthreads();

    int* pa = HA; int* pb = HB;
    #pragma unroll
    for (int off = 1; off < NBKT; off <<= 1) {
        pb[t] = pa[t] + ((t >= off) ? pa[t - off] : 0);
        __syncthreads();
        int* tmp = pa; pa = pb; pb = tmp;
    }
    if (t == 0) g_boff[0] = 0;
    g_boff[t + 1] = pa[t];
    pb[t] = (t > 0) ? pa[t - 1] : 0;       // per-bucket running cursors
    __syncthreads();

    #pragma unroll
    for (int e = 0; e < 8; e++)
        if (rb[e] >= 0) rpos[e] = atomicAdd(&pb[rb[e]], 1);
    __syncthreads();

    // pass 1: u
    #pragma unroll
    for (int e = 0; e < 8; e++) if (rb[e] >= 0) SG[rpos[e]] = rp[e] * K1;
    __syncthreads();
    #pragma unroll
    for (int e = 0; e < 8; e++) { int i = t + e * 1024; if (i < n) st_u[i] = SG[i]; }
    __syncthreads();
    // pass 2: z = -u*yt
    #pragma unroll
    for (int e = 0; e < 8; e++) if (rb[e] >= 0) SG[rpos[e]] = -(rp[e] * K1) * ry[e];
    __syncthreads();
    #pragma unroll
    for (int e = 0; e < 8; e++) { int i = t + e * 1024; if (i < n) st_z[i] = SG[i]; }
    __syncthreads();
    // pass 3: yt
    #pragma unroll
    for (int e = 0; e < 8; e++) if (rb[e] >= 0) SG[rpos[e]] = ry[e];
    __syncthreads();
    #pragma unroll
    for (int e = 0; e < 8; e++) { int i = t + e * 1024; if (i < n) st_yt[i] = SG[i]; }
    // padding
    for (int i = n + t; i < padn; i += 1024) { st_u[i] = 0.f; st_z[i] = 0.f; st_yt[i] = 1e30f; }

    // global min
    #pragma unroll
    for (int o = 16; o; o >>= 1) mn = fminf(mn, __shfl_xor_sync(0xffffffffu, mn, o));
    if ((t & 31) == 0) smn[t >> 5] = mn;
    __syncthreads();
    if (t < 32) {
        float v = smn[t];
        #pragma unroll
        for (int o = 16; o; o >>= 1) v = fminf(v, __shfl_xor_sync(0xffffffffu, v, o));
        if (t == 0) g_ymin = v;
    }
}

// ------------- Main: adjacent-rank pairs, strided balance, smem u/z ----------
__global__ void __launch_bounds__(TPB) pro_main(float* __restrict__ out,
                                                int n, int padn, int grid)
{
    extern __shared__ __align__(16) char smem_raw[];
    float4* su4 = (float4*)smem_raw;                    // 32 KB u
    float4* sz4 = (float4*)(smem_raw + NMAX * 4);       // 32 KB z

    __shared__ float rlp[SLOTS], rct[SLOTS];
    __shared__ int   s_last;
    __shared__ float ft[SLOTS], fc[SLOTS];

    const float EPS = 1e-8f;
    const float LN2 = 0.6931471805599453f;
    int t = threadIdx.x, w = t >> 5, l = t & 31;
    int nslots = (n + 1) >> 1;
    int q = blockIdx.x + grid * w;          // strided slot assignment (balance)
    bool hasQ = (q < nslots);

    // stage sorted u and z into separate smem arrays (conflict-free layout)
    {
        const float4* gu = (const float4*)st_u;
        const float4* gz = (const float4*)st_z;
        int ngrp = padn >> 2;
        for (int i = t; i < ngrp; i += TPB) { su4[i] = gu[i]; sz4[i] = gz[i]; }
    }

    int r0 = 2 * q, r1 = 2 * q + 1;
    bool has0 = hasQ && (r0 < n);
    bool has1 = hasQ && (r1 < n);

    float yt0 = 0.f, u0v = 0.f, e0 = 0.f; int cLo0 = 0, cHi0 = 0;
    float yt1 = 0.f, u1v = 0.f, e1 = 0.f; int cLo1 = 0, cHi1 = 0;
    if (has0) {
        yt0 = st_yt[r0]; u0v = st_u[r0]; e0 = yt0 - EPS;
        int b = min(NBKT - 1, max(0, (int)floorf(e0 * (float)NBKT)));
        cLo0 = g_boff[b]; cHi0 = g_boff[b + 1];
    }
    if (has1) {
        yt1 = st_yt[r1]; u1v = st_u[r1]; e1 = yt1 - EPS;
        int b = min(NBKT - 1, max(0, (int)floorf(e1 * (float)NBKT)));
        cLo1 = g_boff[b]; cHi1 = g_boff[b + 1];
    } else { yt1 = yt0; e1 = e0; cLo1 = cLo0; cHi1 = cLo0; }

    __syncthreads();                            // staging complete

    // adjacent ranks => cLo0 <= cLo1 (yt sorted ascending)
    int G1 = cLo0 >> 2;            // groups fully valid for BOTH rows
    int G2 = cLo1 >> 2;            // groups fully valid for row1

    float a0 = 0.f, a1 = 0.f, a2 = 0.f, a3 = 0.f;   // row0 accumulators
    float b0 = 0.f, b1 = 0.f, b2 = 0.f, b3 = 0.f;   // row1 accumulators

    if (has0) {
        // shared fast loop: 8 exps per 2 conflict-free LDS.128, 8 accumulators
        #pragma unroll 2
        for (int g = l; g < G1; g += 32) {
            float4 uu = su4[g], zz = sz4[g];
            a0 += ex2a(fmaf(yt0, uu.x, zz.x));
            a1 += ex2a(fmaf(yt0, uu.y, zz.y));
            a2 += ex2a(fmaf(yt0, uu.z, zz.z));
            a3 += ex2a(fmaf(yt0, uu.w, zz.w));
            b0 += ex2a(fmaf(yt1, uu.x, zz.x));
            b1 += ex2a(fmaf(yt1, uu.y, zz.y));
            b2 += ex2a(fmaf(yt1, uu.z, zz.z));
            b3 += ex2a(fmaf(yt1, uu.w, zz.w));
        }
        // row1-only fast groups (tiny: ranks adjacent, cutoffs near-equal)
        for (int g = G1 + l; g < G2; g += 32) {
            float4 uu = su4[g], zz = sz4[g];
            b0 += ex2a(fmaf(yt1, uu.x, zz.x));
            b1 += ex2a(fmaf(yt1, uu.y, zz.y));
            b2 += ex2a(fmaf(yt1, uu.z, zz.z));
            b3 += ex2a(fmaf(yt1, uu.w, zz.w));
        }
        // row0 masked: elements [4*G1, cHi0)
        for (int i = 4 * G1 + l; i < cHi0; i += 32) {
            float v = ex2a(fmaf(yt0, st_u[i], st_z[i]));
            if (st_yt[i] < e0) a0 += v;
        }
        // row1 masked: elements [4*G2, cHi1)
        for (int i = 4 * G2 + l; i < cHi1; i += 32) {
            float v = ex2a(fmaf(yt1, st_u[i], st_z[i]));
            if (st_yt[i] < e1) b0 += v;
        }
    }

    // warp reduce (full warp, full mask)
    float s0 = (a0 + a1) + (a2 + a3);
    float s1 = (b0 + b1) + (b2 + b3);
    #pragma unroll
    for (int o = 16; o; o >>= 1) {
        s0 += __shfl_xor_sync(0xffffffffu, s0, o);
        s1 += __shfl_xor_sync(0xffffffffu, s1, o);
    }

    if (l == 0) {
        float lp = 0.f, c = 0.f;
        float ymin = g_ymin;
        if (has0) {
            float d = yt0 - ymin;
            if (d > EPS) {
                float wv = u0v * d;                  // log2 of exp(logit_pos)
                lp += wv * LN2 - logf(ex2a(wv) + s0);
                c  += 1.f;
            }
        }
        if (has1) {
            float d = yt1 - ymin;
            if (d > EPS) {
                float wv = u1v * d;
                lp += wv * LN2 - logf(ex2a(wv) + s1);
                c  += 1.f;
            }
        }
        rlp[w] = lp; rct[w] = c;
    }
    __syncthreads();

    // publish per-CTA partial, elect last block
    if (t == 0) {
        float tot = 0.f, c = 0.f;
        #pragma unroll
        for (int i = 0; i < SLOTS; i++) { tot += rlp[i]; c += rct[i]; }
        g_part[blockIdx.x] = make_float2(tot, c);
        __threadfence();
        int done = atomicAdd(&g_done, 1);
        s_last = (done == grid - 1) ? 1 : 0;
    }
    __syncthreads();

    // last block: deterministic final reduce
    if (s_last) {
        __threadfence();
        float tot = 0.f, cnt = 0.f;
        for (int i = t; i < grid; i += TPB) {
            float2 p = g_part[i]; tot += p.x; cnt += p.y;
        }
        #pragma unroll
        for (int o = 16; o; o >>= 1) {            // all threads, full warps
            tot += __shfl_xor_sync(0xffffffffu, tot, o);
            cnt += __shfl_xor_sync(0xffffffffu, cnt, o);
        }
        if ((t & 31) == 0) { ft[t >> 5] = tot; fc[t >> 5] = cnt; }
        __syncthreads();
        if (t == 0) {
            float a = 0.f, b = 0.f;
            #pragma unroll
            for (int i = 0; i < SLOTS; i++) { a += ft[i]; b += fc[i]; }
            out[0] = (b > 0.f) ? (-a / b) : 0.0f;
            g_done = 0;   // restore for next graph replay
        }
    }
}

// ------------- Launch --------------------------------------------------------
extern "C" void kernel_launch(void* const* d_in, const int* in_sizes, int n_in,
                              void* d_out, int out_size)
{
    const float* pred = (const float*)d_in[0];   // predict_similarity
    const float* yt   = (const float*)d_in[1];   // true_similarity
    int n = in_sizes[0];
    if (n > NMAX) n = NMAX;
    int padn = (n + 7) & ~7;
    if (padn > NMAX) padn = NMAX;

    int nslots = (n + 1) / 2;                    // 4096 adjacent-rank slots
    int grid = (nslots + SLOTS - 1) / SLOTS;     // 147 -> one CTA per SM, one wave
    if (grid > GMAX) grid = GMAX;

    static int smem_set = 0;
    if (!smem_set) {
        cudaFuncSetAttribute(pro_main, cudaFuncAttributeMaxDynamicSharedMemorySize,
                             (int)SMEM_BYTES);
        smem_set = 1;
    }

    pro_prep<<<1, 1024>>>(pred, yt, n, padn);
    pro_main<<<grid, TPB, SMEM_BYTES>>>((float*)d_out, n, padn, grid);
}

// round 17
// speedup vs baseline: 1.1946x; 1.1946x over previous
#include <cuda_runtime.h>
#include <math.h>

#define NMAX  8192
#define NBKT  1024
#define TPB   896     // 28 warps; 1 warp = 1 row-pair slot (q, n-1-q)
#define SLOTS 28
#define GMAX  512
#define SMEM_BYTES (NMAX * 3 * sizeof(float))   // 96 KB: su + sz + syt

__device__ float2 g_part[GMAX];
__device__ int    g_done;             // zero-init; reset by last block each run

__device__ __forceinline__ float ex2a(float x) {
    float r; asm("ex2.approx.f32 %0, %1;" : "=f"(r) : "f"(x)); return r;
}

// ------------- Single fused kernel: per-CTA smem sort + O(N^2) + finish ------
__global__ void __launch_bounds__(TPB) pro_fused(const float* __restrict__ pred,
                                                 const float* __restrict__ ytg,
                                                 float* __restrict__ out,
                                                 int n, int grid)
{
    extern __shared__ __align__(16) char smem_raw[];
    float* su  = (float*)smem_raw;                    // 32 KB sorted u
    float* sz  = (float*)(smem_raw + NMAX * 4);       // 32 KB sorted z
    float* syt = (float*)(smem_raw + NMAX * 8);       // 32 KB sorted yt
    float4* su4 = (float4*)su;
    float4* sz4 = (float4*)sz;

    __shared__ int   sh[NBKT + 1];     // bucket offsets (exclusive scan)
    __shared__ int   scur[NBKT];       // scatter cursors
    __shared__ float smn[SLOTS];
    __shared__ float s_min;
    __shared__ float rlp[SLOTS], rct[SLOTS];
    __shared__ int   s_last;
    __shared__ float ft[SLOTS], fc[SLOTS];

    const float EPS = 1e-8f;
    const float LN2 = 0.6931471805599453f;
    const float K1  = 28.853900817779268f;   // 20 * log2(e)
    int t = threadIdx.x, w = t >> 5, l = t & 31;

    // ---- phase 1: histogram + min ----
    for (int i = t; i < NBKT; i += TPB) sh[i] = 0;
    __syncthreads();

    float mn = 1e30f;
    for (int i = t; i < n; i += TPB) {
        float y = ytg[i];
        mn = fminf(mn, y);
        int b = min(NBKT - 1, max(0, (int)floorf(y * (float)NBKT)));
        atomicAdd(&sh[b], 1);
    }
    #pragma unroll
    for (int o = 16; o; o >>= 1) mn = fminf(mn, __shfl_xor_sync(0xffffffffu, mn, o));
    if (l == 0) smn[w] = mn;
    __syncthreads();

    // ---- phase 2: exclusive scan of 1024 buckets (warp 0, chunked) ----
    if (w == 0) {
        int base = l * 32;
        int acc = 0;
        #pragma unroll
        for (int j = 0; j < 32; j++) { int v = sh[base + j]; sh[base + j] = acc; acc += v; }
        int tot = acc;
        #pragma unroll
        for (int o = 1; o < 32; o <<= 1) {
            int nv = __shfl_up_sync(0xffffffffu, tot, o);
            if (l >= o) tot += nv;
        }
        int excl = tot - acc;
        #pragma unroll
        for (int j = 0; j < 32; j++) sh[base + j] += excl;
        if (l == 31) sh[NBKT] = n;
        // block min finalize (28 partials)
        float v = 1e30f;
        if (l < SLOTS) v = smn[l];
        #pragma unroll
        for (int o = 16; o; o >>= 1) v = fminf(v, __shfl_xor_sync(0xffffffffu, v, o));
        if (l == 0) s_min = v;
    }
    __syncthreads();

    // ---- phase 3: copy cursors, scatter into sorted smem arrays ----
    for (int i = t; i < NBKT; i += TPB) scur[i] = sh[i];
    __syncthreads();

    for (int i = t; i < n; i += TPB) {
        float y = ytg[i], p = pred[i];
        int b = min(NBKT - 1, max(0, (int)floorf(y * (float)NBKT)));
        int pos = atomicAdd(&scur[b], 1);
        float u = p * K1;
        su[pos] = u; sz[pos] = -u * y; syt[pos] = y;
    }
    __syncthreads();

    // ---- phase 4: main O(N^2) pass (R15 structure: opposing pairs) ----
    int q = blockIdx.x * SLOTS + w;
    bool hasA = (2 * q <= n - 1);
    bool hasB = (2 * q <  n - 1);
    int rA = q, rB = n - 1 - q;

    float ytA = 0.f, uA = 0.f, eA = 0.f; int cLoA = 0, cHiA = 0;
    float ytB = 0.f, uB = 0.f, eB = 0.f; int cLoB = 0, cHiB = 0;
    if (hasA) {
        ytA = syt[rA]; uA = su[rA]; eA = ytA - EPS;
        int b = min(NBKT - 1, max(0, (int)floorf(eA * (float)NBKT)));
        cLoA = sh[b]; cHiA = sh[b + 1];
    }
    if (hasB) {
        ytB = syt[rB]; uB = su[rB]; eB = ytB - EPS;
        int b = min(NBKT - 1, max(0, (int)floorf(eB * (float)NBKT)));
        cLoB = sh[b]; cHiB = sh[b + 1];
    } else { ytB = ytA; eB = eA; cLoB = cLoA; cHiB = cLoA; }

    float aA = 0.f, aA2 = 0.f, aB = 0.f, aB2 = 0.f;

    int G1  = cLoA >> 2;            // groups fully valid for BOTH rows
    int G2  = cLoB >> 2;            // groups fully valid for B

    if (hasA) {
        // shared fast loop: 8 exps per 2 conflict-free LDS.128
        #pragma unroll 2
        for (int g = l; g < G1; g += 32) {
            float4 u0 = su4[g], z0 = sz4[g];
            aA  += ex2a(fmaf(ytA, u0.x, z0.x));
            aA2 += ex2a(fmaf(ytA, u0.y, z0.y));
            aA  += ex2a(fmaf(ytA, u0.z, z0.z));
            aA2 += ex2a(fmaf(ytA, u0.w, z0.w));
            aB  += ex2a(fmaf(ytB, u0.x, z0.x));
            aB2 += ex2a(fmaf(ytB, u0.y, z0.y));
            aB  += ex2a(fmaf(ytB, u0.z, z0.z));
            aB2 += ex2a(fmaf(ytB, u0.w, z0.w));
        }
        // B-only fast loop
        #pragma unroll 2
        for (int g = G1 + l; g < G2; g += 32) {
            float4 u0 = su4[g], z0 = sz4[g];
            aB  += ex2a(fmaf(ytB, u0.x, z0.x));
            aB2 += ex2a(fmaf(ytB, u0.y, z0.y));
            aB  += ex2a(fmaf(ytB, u0.z, z0.z));
            aB2 += ex2a(fmaf(ytB, u0.w, z0.w));
        }
        // A masked bucket (tiny, element-wise)
        for (int i = 4 * G1 + l; i < cHiA; i += 32) {
            float v = ex2a(fmaf(ytA, su[i], sz[i]));
            if (syt[i] < eA) aA += v;
        }
        // B masked bucket
        for (int i = 4 * G2 + l; i < cHiB; i += 32) {
            float v = ex2a(fmaf(ytB, su[i], sz[i]));
            if (syt[i] < eB) aB += v;
        }
    }

    // warp reduce (full warp, full mask)
    float sA = aA + aA2;
    float sB = aB + aB2;
    #pragma unroll
    for (int o = 16; o; o >>= 1) {
        sA += __shfl_xor_sync(0xffffffffu, sA, o);
        sB += __shfl_xor_sync(0xffffffffu, sB, o);
    }

    if (l == 0) {
        float lp = 0.f, c = 0.f;
        float ymin = s_min;
        if (hasA) {
            float d = ytA - ymin;
            if (d > EPS) {
                float wv = uA * d;                   // log2 of exp(logit_pos)
                lp += wv * LN2 - logf(ex2a(wv) + sA);
                c  += 1.f;
            }
        }
        if (hasB) {
            float d = ytB - ymin;
            if (d > EPS) {
                float wv = uB * d;
                lp += wv * LN2 - logf(ex2a(wv) + sB);
                c  += 1.f;
            }
        }
        rlp[w] = lp; rct[w] = c;
    }
    __syncthreads();

    // publish per-CTA partial, elect last block
    if (t == 0) {
        float tot = 0.f, c = 0.f;
        #pragma unroll
        for (int i = 0; i < SLOTS; i++) { tot += rlp[i]; c += rct[i]; }
        g_part[blockIdx.x] = make_float2(tot, c);
        __threadfence();
        int done = atomicAdd(&g_done, 1);
        s_last = (done == grid - 1) ? 1 : 0;
    }
    __syncthreads();

    // last block: deterministic final reduce
    if (s_last) {
        __threadfence();
        float tot = 0.f, cnt = 0.f;
        for (int i = t; i < grid; i += TPB) {
            float2 p = g_part[i]; tot += p.x; cnt += p.y;
        }
        #pragma unroll
        for (int o = 16; o; o >>= 1) {            // all threads, full warps
            tot += __shfl_xor_sync(0xffffffffu, tot, o);
            cnt += __shfl_xor_sync(0xffffffffu, cnt, o);
        }
        if ((t & 31) == 0) { ft[t >> 5] = tot; fc[t >> 5] = cnt; }
        __syncthreads();
        if (t == 0) {
            float a = 0.f, b = 0.f;
            #pragma unroll
            for (int i = 0; i < SLOTS; i++) { a += ft[i]; b += fc[i]; }
            out[0] = (b > 0.f) ? (-a / b) : 0.0f;
            g_done = 0;   // restore for next graph replay
        }
    }
}

// ------------- Launch --------------------------------------------------------
extern "C" void kernel_launch(void* const* d_in, const int* in_sizes, int n_in,
                              void* d_out, int out_size)
{
    const float* pred = (const float*)d_in[0];   // predict_similarity
    const float* yt   = (const float*)d_in[1];   // true_similarity
    int n = in_sizes[0];
    if (n > NMAX) n = NMAX;

    int nslots = (n + 1) / 2;                    // 4096 row-pair slots
    int grid = (nslots + SLOTS - 1) / SLOTS;     // 147 -> one CTA per SM, one wave
    if (grid > GMAX) grid = GMAX;

    static int smem_set = 0;
    if (!smem_set) {
        cudaFuncSetAttribute(pro_fused, cudaFuncAttributeMaxDynamicSharedMemorySize,
                             (int)SMEM_BYTES);
        smem_set = 1;
    }

    pro_fused<<<grid, TPB, SMEM_BYTES>>>(pred, yt, (float*)d_out, n, grid);
}